// round 1
// baseline (speedup 1.0000x reference)
#include <cuda_runtime.h>
#include <cuda_bf16.h>
#include <mma.h>

using namespace nvcuda;

#define NN   32768
#define DD   128
#define BB   64
#define NPGC 512
#define EE   524288
#define KCL  5
#define H2D  256
#define CBN  512

// ---------------- scratch (device globals; no runtime allocation) ----------------
__device__ float          g_h[NN*DD];
__device__ __nv_bfloat16  g_ahi[NN*DD],  g_alo[NN*DD];     // activation split (K=128 inputs)
__device__ __nv_bfloat16  g_bhi[NN*H2D], g_blo[NN*H2D];    // hidden split (K=256 inputs)
__device__ float          g_cl1[NN*64];
__device__ float          g_S[NN*KCL];
__device__ float          g_cf[BB*KCL*DD];
__device__ float          g_zq[BB*KCL*DD];
__device__ float          g_res[BB*DD];
__device__ int            g_indeg[NN], g_cur[NN], g_off[NN+1], g_srcl[EE], g_bsum[256];
__device__ __nv_bfloat16  g_w1hi[3*DD*H2D], g_w1lo[3*DD*H2D];
__device__ __nv_bfloat16  g_w2hi[3*H2D*DD], g_w2lo[3*H2D*DD];
__device__ __nv_bfloat16  g_pwhi[DD*64],    g_pwlo[DD*64];
__device__ float          g_pb1[64];

__device__ __forceinline__ void bsplit(float v, __nv_bfloat16& hi, __nv_bfloat16& lo) {
    hi = __float2bfloat16(v);
    lo = __float2bfloat16(v - __bfloat162float(hi));
}

// ---------------- CSR build ----------------
__global__ void zero_kernel() {
    int i = blockIdx.x*256 + threadIdx.x;
    if (i < NN) g_indeg[i] = 0;
}
__global__ void count_kernel(const int* __restrict__ ei) {
    int e = blockIdx.x*256 + threadIdx.x;
    if (e < EE) atomicAdd(&g_indeg[ei[EE + e]], 1);
}
__global__ void scan1_kernel() {
    __shared__ int s[128];
    int t = threadIdx.x, i = blockIdx.x*128 + t;
    s[t] = g_indeg[i];
    __syncthreads();
    for (int off = 1; off < 128; off <<= 1) {
        int v = (t >= off) ? s[t-off] : 0;
        __syncthreads();
        s[t] += v;
        __syncthreads();
    }
    g_off[i] = s[t];
    if (t == 127) g_bsum[blockIdx.x] = s[127];
}
__global__ void scan2_kernel() {
    __shared__ int s[256];
    int t = threadIdx.x;
    s[t] = g_bsum[t];
    __syncthreads();
    for (int off = 1; off < 256; off <<= 1) {
        int v = (t >= off) ? s[t-off] : 0;
        __syncthreads();
        s[t] += v;
        __syncthreads();
    }
    g_bsum[t] = s[t];
}
__global__ void scan3_kernel() {
    int t = threadIdx.x, b = blockIdx.x;
    int i = b*128 + t;
    int excl = g_off[i] - g_indeg[i] + (b ? g_bsum[b-1] : 0);
    g_off[i] = excl;
    g_cur[i] = excl;
    if (b == 255 && t == 127) g_off[NN] = g_bsum[255];
}
__global__ void scatter_kernel(const int* __restrict__ ei) {
    int e = blockIdx.x*256 + threadIdx.x;
    if (e >= EE) return;
    int d = ei[EE + e];
    int p = atomicAdd(&g_cur[d], 1);
    g_srcl[p] = ei[e];
}

// ---------------- weight split prep ----------------
__global__ void prep_kernel(const float* __restrict__ gW1, const float* __restrict__ gW2,
                            const float* __restrict__ pW1, const float* __restrict__ pb1) {
    int i = blockIdx.x*blockDim.x + threadIdx.x;
    if (i < 3*DD*H2D) { bsplit(gW1[i], g_w1hi[i], g_w1lo[i]); return; }
    i -= 3*DD*H2D;
    if (i < 3*H2D*DD) { bsplit(gW2[i], g_w2hi[i], g_w2lo[i]); return; }
    i -= 3*H2D*DD;
    if (i < DD*64) {
        int rw = i >> 6, cl = i & 63;
        float v = (cl < 50) ? pW1[rw*50 + cl] : 0.0f;
        bsplit(v, g_pwhi[i], g_pwlo[i]);
        return;
    }
    i -= DD*64;
    if (i < 64) g_pb1[i] = (i < 50) ? pb1[i] : 0.0f;
}

// ---------------- embedding ----------------
__global__ void embed_kernel(const int* __restrict__ x, const float* __restrict__ emb) {
    int i = blockIdx.x*256 + threadIdx.x;     // < NN*DD
    g_h[i] = emb[x[i >> 7]*DD + (i & 127)];
}

// ---------------- per-node gather (z = h + sum incoming) + bf16 split ----------------
__global__ void gather_kernel() {
    int w = threadIdx.x >> 5, lane = threadIdx.x & 31;
    int node = blockIdx.x*8 + w;
    const float4* h4 = (const float4*)g_h;
    float4 a = h4[(size_t)node*32 + lane];
    int e0 = g_off[node], e1 = g_off[node+1];
    for (int j = e0; j < e1; j++) {
        int s = g_srcl[j];
        float4 v = h4[(size_t)s*32 + lane];
        a.x += v.x; a.y += v.y; a.z += v.z; a.w += v.w;
    }
    __nv_bfloat162* ph = (__nv_bfloat162*)g_ahi;
    __nv_bfloat162* pl = (__nv_bfloat162*)g_alo;
    __nv_bfloat16 h0,l0,h1,l1;
    bsplit(a.x, h0, l0); bsplit(a.y, h1, l1);
    ph[(size_t)node*64 + lane*2]     = __halves2bfloat162(h0, h1);
    pl[(size_t)node*64 + lane*2]     = __halves2bfloat162(l0, l1);
    bsplit(a.z, h0, l0); bsplit(a.w, h1, l1);
    ph[(size_t)node*64 + lane*2 + 1] = __halves2bfloat162(h0, h1);
    pl[(size_t)node*64 + lane*2 + 1] = __halves2bfloat162(l0, l1);
}

// ---------------- bf16-split GEMM (wmma), 128x64 block tile ----------------
// flags: 1=relu, 2=BN affine, 4=write fp32, 8=write bf16 hi/lo split
__global__ void gemm_split(const __nv_bfloat16* __restrict__ Ahi, const __nv_bfloat16* __restrict__ Alo,
                           const __nv_bfloat16* __restrict__ Bhi, const __nv_bfloat16* __restrict__ Blo,
                           const float* __restrict__ bias, const float* __restrict__ gamma,
                           const float* __restrict__ beta,
                           float* __restrict__ outF, __nv_bfloat16* __restrict__ outHi,
                           __nv_bfloat16* __restrict__ outLo,
                           int M, int Nn, int K, int flags)
{
    __shared__ __align__(16) __nv_bfloat16 sA[128*24];
    __shared__ __align__(16) __nv_bfloat16 sB[16*72];
    __shared__ __align__(16) float         sO[128*68];
    int t = threadIdx.x;
    int m0 = blockIdx.x*128, n0 = blockIdx.y*64;
    int w = t >> 5, wm = w & 3, wn = w >> 2;

    wmma::fragment<wmma::accumulator,16,16,16,float> acc[2][2];
    #pragma unroll
    for (int i = 0; i < 2; i++)
        #pragma unroll
        for (int j = 0; j < 2; j++)
            wmma::fill_fragment(acc[i][j], 0.0f);

    for (int s = 0; s < 3; s++) {
        const __nv_bfloat16* Ap = (s == 2) ? Alo : Ahi;
        const __nv_bfloat16* Bp = (s == 1) ? Blo : Bhi;
        for (int kb = 0; kb < K; kb += 16) {
            {
                int r = t >> 1, p = t & 1;
                *(uint4*)(sA + r*24 + p*8) = *(const uint4*)(Ap + (size_t)(m0 + r)*K + kb + p*8);
            }
            if (t < 128) {
                int br = t >> 3, bp = t & 7;
                *(uint4*)(sB + br*72 + bp*8) = *(const uint4*)(Bp + (size_t)(kb + br)*Nn + n0 + bp*8);
            }
            __syncthreads();
            wmma::fragment<wmma::matrix_a,16,16,16,__nv_bfloat16,wmma::row_major> af[2];
            wmma::fragment<wmma::matrix_b,16,16,16,__nv_bfloat16,wmma::row_major> bf[2];
            wmma::load_matrix_sync(af[0], sA + (wm*32)*24,      24);
            wmma::load_matrix_sync(af[1], sA + (wm*32 + 16)*24, 24);
            wmma::load_matrix_sync(bf[0], sB + wn*32,      72);
            wmma::load_matrix_sync(bf[1], sB + wn*32 + 16, 72);
            #pragma unroll
            for (int i = 0; i < 2; i++)
                #pragma unroll
                for (int j = 0; j < 2; j++)
                    wmma::mma_sync(acc[i][j], af[i], bf[j], acc[i][j]);
            __syncthreads();
        }
    }

    #pragma unroll
    for (int i = 0; i < 2; i++)
        #pragma unroll
        for (int j = 0; j < 2; j++)
            wmma::store_matrix_sync(sO + (wm*32 + i*16)*68 + wn*32 + j*16, acc[i][j], 68, wmma::mem_row_major);
    __syncthreads();

    const float BNS = 0.99999500003749971f;   // 1/sqrt(1+1e-5)
    for (int idx = t; idx < 128*64; idx += 256) {
        int rr = idx >> 6, cc = idx & 63;
        float v = sO[rr*68 + cc] + bias[n0 + cc];
        if (flags & 2) v = v*(BNS*gamma[n0 + cc]) + beta[n0 + cc];
        if (flags & 1) v = fmaxf(v, 0.0f);
        size_t gi = (size_t)(m0 + rr)*Nn + n0 + cc;
        if (flags & 4) outF[gi] = v;
        if (flags & 8) {
            __nv_bfloat16 hi = __float2bfloat16(v);
            outHi[gi] = hi;
            outLo[gi] = __float2bfloat16(v - __bfloat162float(hi));
        }
    }
}

// ---------------- partitioner stage 2: logits + softmax ----------------
__global__ void part2_kernel(const float* __restrict__ pW2, const float* __restrict__ pb2) {
    __shared__ float w2s[250], b2s[5];
    int t = threadIdx.x;
    for (int i = t; i < 255; i += 128) {
        if (i < 250) w2s[i] = pW2[i];
        else         b2s[i-250] = pb2[i-250];
    }
    __syncthreads();
    int node = blockIdx.x*128 + t;
    const float* rowp = g_cl1 + (size_t)node*64;
    float cr[50];
    #pragma unroll
    for (int j = 0; j < 50; j++) cr[j] = rowp[j];
    float l[5];
    #pragma unroll
    for (int k = 0; k < 5; k++) {
        float a = b2s[k];
        #pragma unroll
        for (int j = 0; j < 50; j++) a += cr[j]*w2s[j*5 + k];
        l[k] = a;
    }
    float m = l[0];
    #pragma unroll
    for (int k = 1; k < 5; k++) m = fmaxf(m, l[k]);
    float e[5], s = 0.0f;
    #pragma unroll
    for (int k = 0; k < 5; k++) { e[k] = expf(l[k] - m); s += e[k]; }
    float inv = 1.0f/s;
    #pragma unroll
    for (int k = 0; k < 5; k++) g_S[(size_t)node*5 + k] = e[k]*inv;
}

// ---------------- soft-cluster pooling: cf[b,k,:] = S^T dense / (sumS+eps) ----------------
__global__ void cf_kernel() {
    int g = blockIdx.x, t = threadIdx.x;     // 640 threads
    __shared__ float sh[64*128];
    __shared__ float sS[64*5];
    int k = t >> 7, c = t & 127;
    float acc = 0.0f, ss = 0.0f;
    for (int ch = 0; ch < 8; ch++) {
        int nb = ch*64;
        const float* hb = g_h + ((size_t)g*NPGC + nb)*DD;
        for (int i = t; i < 64*128; i += 640) sh[i] = hb[i];
        const float* sb = g_S + ((size_t)g*NPGC + nb)*5;
        for (int i = t; i < 320; i += 640) sS[i] = sb[i];
        __syncthreads();
        for (int n2 = 0; n2 < 64; n2++) {
            float s = sS[n2*5 + k];
            acc += s*sh[n2*128 + c];
            ss  += s;
        }
        __syncthreads();
    }
    g_cf[((size_t)g*5 + k)*128 + c] = acc/(ss + 1e-6f);
}

// ---------------- VQ nearest codebook ----------------
__global__ void vq_kernel(const float* __restrict__ codebook) {
    int row = blockIdx.x;                    // 0..319
    int t = threadIdx.x, w = t >> 5, lane = t & 31;
    __shared__ __align__(16) float f[128];
    __shared__ float wbest[4];
    __shared__ int   widx[4];
    __shared__ int   bestidx;
    f[t] = g_cf[(size_t)row*128 + t];
    __syncthreads();
    float4 fv = ((const float4*)f)[lane];
    float best = 3.4e38f;
    int bi = 0;
    for (int rr = w; rr < CBN; rr += 4) {
        const float4* cb4 = (const float4*)(codebook + (size_t)rr*128);
        float4 cv = cb4[lane];
        float dx = cv.x - fv.x, dy = cv.y - fv.y, dz = cv.z - fv.z, dw = cv.w - fv.w;
        float d = dx*dx + dy*dy + dz*dz + dw*dw;
        #pragma unroll
        for (int o = 16; o; o >>= 1) d += __shfl_xor_sync(0xffffffff, d, o);
        if (d < best) { best = d; bi = rr; }
    }
    if (lane == 0) { wbest[w] = best; widx[w] = bi; }
    __syncthreads();
    if (t == 0) {
        float bb = wbest[0]; int ii = widx[0];
        for (int j = 1; j < 4; j++)
            if (wbest[j] < bb || (wbest[j] == bb && widx[j] < ii)) { bb = wbest[j]; ii = widx[j]; }
        bestidx = ii;
    }
    __syncthreads();
    g_zq[(size_t)row*128 + t] = codebook[(size_t)bestidx*128 + t];
}

// ---------------- scatter-mean pooling ----------------
__global__ void residue_kernel() {
    int g = blockIdx.x, t = threadIdx.x;
    const float* base = g_h + (size_t)g*NPGC*DD + t;
    float a = 0.0f;
    for (int n2 = 0; n2 < NPGC; n2++) a += base[(size_t)n2*DD];
    g_res[g*DD + t] = a*(1.0f/NPGC);
}

// ---------------- fused attention + gate + classifier (per-graph) ----------------
__global__ void tail_kernel(const float* __restrict__ Wq, const float* __restrict__ Wk,
                            const float* __restrict__ Wv, const float* __restrict__ Wo,
                            const float* __restrict__ gW1, const float* __restrict__ gb1,
                            const float* __restrict__ gW2, const float* __restrict__ gb2,
                            const float* __restrict__ cW1, const float* __restrict__ cb1,
                            const float* __restrict__ cW2, const float* __restrict__ cb2,
                            const float* __restrict__ cW3, const float* __restrict__ cb3,
                            float* __restrict__ out)
{
    int g = blockIdx.x, t = threadIdx.x;     // 128 threads
    __shared__ float r[128], zq5[5*128], qv[128], kk[5*128], vv[5*128];
    __shared__ float sc[20], aw[20], attv[128], attn[128], g1[64], fused[128];
    __shared__ float z1[512], z2[256];

    r[t] = g_res[g*128 + t];
    #pragma unroll
    for (int j = 0; j < 5; j++) zq5[j*128 + t] = g_zq[((size_t)g*5 + j)*128 + t];
    __syncthreads();

    { // q
        float a = 0.0f;
        for (int k2 = 0; k2 < 128; k2++) a += r[k2]*Wq[k2*128 + t];
        qv[t] = a;
    }
    { // k
        float a5[5] = {0,0,0,0,0};
        for (int k2 = 0; k2 < 128; k2++) {
            float wv2 = Wk[k2*128 + t];
            #pragma unroll
            for (int j = 0; j < 5; j++) a5[j] += zq5[j*128 + k2]*wv2;
        }
        #pragma unroll
        for (int j = 0; j < 5; j++) kk[j*128 + t] = a5[j];
    }
    { // v
        float a5[5] = {0,0,0,0,0};
        for (int k2 = 0; k2 < 128; k2++) {
            float wv2 = Wv[k2*128 + t];
            #pragma unroll
            for (int j = 0; j < 5; j++) a5[j] += zq5[j*128 + k2]*wv2;
        }
        #pragma unroll
        for (int j = 0; j < 5; j++) vv[j*128 + t] = a5[j];
    }
    __syncthreads();

    if (t < 20) {
        int hh = t/5, j = t%5;
        float s = 0.0f;
        for (int d2 = 0; d2 < 32; d2++) s += qv[hh*32 + d2]*kk[j*128 + hh*32 + d2];
        sc[t] = s*0.17677669529663687f;      // 1/sqrt(32)
    }
    __syncthreads();
    if (t < 4) {
        float m = -1e30f;
        #pragma unroll
        for (int j = 0; j < 5; j++) m = fmaxf(m, sc[t*5 + j]);
        float e[5], s = 0.0f;
        #pragma unroll
        for (int j = 0; j < 5; j++) { e[j] = expf(sc[t*5 + j] - m); s += e[j]; }
        float inv = 1.0f/s;
        #pragma unroll
        for (int j = 0; j < 5; j++) aw[t*5 + j] = e[j]*inv;
    }
    __syncthreads();
    {
        int hh = t >> 5;
        float a = 0.0f;
        #pragma unroll
        for (int j = 0; j < 5; j++) a += aw[hh*5 + j]*vv[j*128 + t];
        attv[t] = a;
    }
    __syncthreads();
    {
        float a = 0.0f;
        for (int k2 = 0; k2 < 128; k2++) a += attv[k2]*Wo[k2*128 + t];
        attn[t] = a;
    }
    __syncthreads();
    if (t < 64) {
        float a = gb1[t];
        for (int k2 = 0; k2 < 128; k2++) a += r[k2]*gW1[k2*64 + t];
        for (int k2 = 0; k2 < 128; k2++) a += attn[k2]*gW1[(128 + k2)*64 + t];
        g1[t] = fmaxf(a, 0.0f);
    }
    __syncthreads();
    {
        float a = gb2[t];
        for (int k2 = 0; k2 < 64; k2++) a += g1[k2]*gW2[k2*128 + t];
        float gg = 1.0f/(1.0f + expf(-a));
        fused[t] = gg*r[t] + (1.0f - gg)*attn[t];
    }
    __syncthreads();
    for (int o = t; o < 512; o += 128) {
        float a = cb1[o];
        for (int k2 = 0; k2 < 128; k2++) a += fused[k2]*cW1[k2*512 + o];
        z1[o] = fmaxf(a, 0.0f);
    }
    __syncthreads();
    for (int o = t; o < 256; o += 128) {
        float a = cb2[o];
        for (int k2 = 0; k2 < 512; k2++) a += z1[k2]*cW2[k2*256 + o];
        z2[o] = fmaxf(a, 0.0f);
    }
    __syncthreads();
    if (t < 2) {
        float a = cb3[t];
        for (int k2 = 0; k2 < 256; k2++) a += z2[k2]*cW3[k2*2 + t];
        out[g*2 + t] = a;
    }
}

// ---------------- host launch ----------------
extern "C" void kernel_launch(void* const* d_in, const int* in_sizes, int n_in,
                              void* d_out, int out_size) {
    (void)in_sizes; (void)n_in; (void)out_size;
    const int*   x     = (const int*)d_in[0];
    const int*   ei    = (const int*)d_in[1];
    const float* emb   = (const float*)d_in[3];
    const float* gW1   = (const float*)d_in[4];
    const float* gb1v  = (const float*)d_in[5];
    const float* gW2   = (const float*)d_in[6];
    const float* gb2v  = (const float*)d_in[7];
    const float* bng   = (const float*)d_in[8];
    const float* bnb   = (const float*)d_in[9];
    const float* pW1   = (const float*)d_in[10];
    const float* pb1   = (const float*)d_in[11];
    const float* pW2   = (const float*)d_in[12];
    const float* pb2   = (const float*)d_in[13];
    const float* Wq    = (const float*)d_in[14];
    const float* Wk    = (const float*)d_in[15];
    const float* Wv    = (const float*)d_in[16];
    const float* Wo    = (const float*)d_in[17];
    const float* gateW1= (const float*)d_in[18];
    const float* gateb1= (const float*)d_in[19];
    const float* gateW2= (const float*)d_in[20];
    const float* gateb2= (const float*)d_in[21];
    const float* cbk   = (const float*)d_in[22];
    const float* cW1   = (const float*)d_in[23];
    const float* cb1   = (const float*)d_in[24];
    const float* cW2   = (const float*)d_in[25];
    const float* cb2   = (const float*)d_in[26];
    const float* cW3   = (const float*)d_in[27];
    const float* cb3   = (const float*)d_in[28];
    float* out = (float*)d_out;

    __nv_bfloat16 *ahi, *alo, *bhi, *blo, *w1hi, *w1lo, *w2hi, *w2lo, *pwhi, *pwlo;
    float *ph, *pcl1, *ppb1;
    cudaGetSymbolAddress((void**)&ahi,  g_ahi);
    cudaGetSymbolAddress((void**)&alo,  g_alo);
    cudaGetSymbolAddress((void**)&bhi,  g_bhi);
    cudaGetSymbolAddress((void**)&blo,  g_blo);
    cudaGetSymbolAddress((void**)&w1hi, g_w1hi);
    cudaGetSymbolAddress((void**)&w1lo, g_w1lo);
    cudaGetSymbolAddress((void**)&w2hi, g_w2hi);
    cudaGetSymbolAddress((void**)&w2lo, g_w2lo);
    cudaGetSymbolAddress((void**)&pwhi, g_pwhi);
    cudaGetSymbolAddress((void**)&pwlo, g_pwlo);
    cudaGetSymbolAddress((void**)&ph,   g_h);
    cudaGetSymbolAddress((void**)&pcl1, g_cl1);
    cudaGetSymbolAddress((void**)&ppb1, g_pb1);

    // CSR build
    zero_kernel   <<<NN/256, 256>>>();
    count_kernel  <<<EE/256, 256>>>(ei);
    scan1_kernel  <<<256, 128>>>();
    scan2_kernel  <<<1, 256>>>();
    scan3_kernel  <<<256, 128>>>();
    scatter_kernel<<<EE/256, 256>>>(ei);

    // weight splits + embedding
    prep_kernel <<<(3*DD*H2D*2 + DD*64 + 64 + 255)/256, 256>>>(gW1, gW2, pW1, pb1);
    embed_kernel<<<NN*DD/256, 256>>>(x, emb);

    // 3 GIN layers
    for (int l = 0; l < 3; l++) {
        gather_kernel<<<NN/8, 256>>>();
        gemm_split<<<dim3(NN/128, H2D/64), 256>>>(
            ahi, alo, w1hi + (size_t)l*DD*H2D, w1lo + (size_t)l*DD*H2D,
            gb1v + l*H2D, nullptr, nullptr,
            nullptr, bhi, blo, NN, H2D, DD, /*relu|split*/ 1 | 8);
        int f2 = 2 | 4 | (l < 2 ? 1 : 0) | (l == 2 ? 8 : 0);
        gemm_split<<<dim3(NN/128, DD/64), 256>>>(
            bhi, blo, w2hi + (size_t)l*H2D*DD, w2lo + (size_t)l*H2D*DD,
            gb2v + l*DD, bng + l*DD, bnb + l*DD,
            ph, ahi, alo, NN, DD, H2D, f2);
    }

    // partitioner stage 1 (padded 50->64)
    gemm_split<<<dim3(NN/128, 1), 256>>>(
        ahi, alo, pwhi, pwlo, ppb1, nullptr, nullptr,
        pcl1, nullptr, nullptr, NN, 64, DD, /*relu|f32*/ 1 | 4);

    part2_kernel  <<<256, 128>>>(pW2, pb2);
    cf_kernel     <<<BB, 640>>>();
    vq_kernel     <<<BB*KCL, 128>>>(cbk);
    residue_kernel<<<BB, 128>>>();
    tail_kernel   <<<BB, 128>>>(Wq, Wk, Wv, Wo, gateW1, gateb1, gateW2, gateb2,
                                cW1, cb1, cW2, cb2, cW3, cb3, out);
}

// round 3
// speedup vs baseline: 1.1814x; 1.1814x over previous
#include <cuda_runtime.h>
#include <cuda_bf16.h>
#include <mma.h>

using namespace nvcuda;

#define NN   32768
#define DD   128
#define BB   64
#define NPGC 512
#define EE   524288
#define KCL  5
#define H2D  256
#define CBN  512

typedef __nv_bfloat16 bf16;

// ---------------- scratch (device globals; no runtime allocation) ----------------
__device__ float g_h[NN*DD];
__device__ bf16  g_ahi[NN*DD],  g_alo[NN*DD];     // activation split (K=128 inputs)
__device__ bf16  g_bhi[NN*H2D], g_blo[NN*H2D];    // hidden split (K=256 inputs)
__device__ float g_S[NN*KCL];
__device__ float g_cf[BB*KCL*DD];
__device__ float g_zq[BB*KCL*DD];
__device__ float g_res[BB*DD];
__device__ int   g_indeg[NN], g_cur[NN], g_off[NN+1], g_srcl[EE];
__device__ bf16  g_w1hi[3*DD*H2D], g_w1lo[3*DD*H2D];
__device__ bf16  g_w2hi[3*H2D*DD], g_w2lo[3*H2D*DD];
__device__ bf16  g_pwhi[DD*128],   g_pwlo[DD*128];   // partitioner W1 padded 50->128
__device__ float g_pb1[128];

__device__ __forceinline__ void bsplit(float v, bf16& hi, bf16& lo) {
    hi = __float2bfloat16(v);
    lo = __float2bfloat16(v - __bfloat162float(hi));
}

// ---------------- CSR build ----------------
__global__ void zero_kernel() {
    int i = blockIdx.x*256 + threadIdx.x;
    if (i < NN) g_indeg[i] = 0;
    int j = i - NN;
    if (j >= 0 && j < BB*DD) g_res[j] = 0.0f;
}
__global__ void count_kernel(const int* __restrict__ ei) {
    int e = blockIdx.x*256 + threadIdx.x;
    if (e < EE) atomicAdd(&g_indeg[ei[EE + e]], 1);
}
// single-block scan of 32768 counters: 1024 threads x 32 sequential
__global__ void scan_kernel() {
    __shared__ int partial[1024];
    int t = threadIdx.x;
    int base = t*32;
    int loc[32];
    int s = 0;
    #pragma unroll
    for (int i = 0; i < 32; i++) { loc[i] = s; s += g_indeg[base + i]; }
    partial[t] = s;
    __syncthreads();
    for (int off = 1; off < 1024; off <<= 1) {
        int v = (t >= off) ? partial[t-off] : 0;
        __syncthreads();
        partial[t] += v;
        __syncthreads();
    }
    int excl = t ? partial[t-1] : 0;
    #pragma unroll
    for (int i = 0; i < 32; i++) {
        int o = excl + loc[i];
        g_off[base + i] = o;
        g_cur[base + i] = o;
    }
    if (t == 1023) g_off[NN] = partial[1023];
}
__global__ void scatter_kernel(const int* __restrict__ ei) {
    int e = blockIdx.x*256 + threadIdx.x;
    if (e >= EE) return;
    int d = ei[EE + e];
    int p = atomicAdd(&g_cur[d], 1);
    g_srcl[p] = ei[e];
}

// ---------------- prep (weight splits) + embedding, merged ----------------
__global__ void prep_embed(const int* __restrict__ x, const float* __restrict__ emb,
                           const float* __restrict__ gW1, const float* __restrict__ gW2,
                           const float* __restrict__ pW1, const float* __restrict__ pb1) {
    int i = blockIdx.x*256 + threadIdx.x;
    if (i < NN*DD) { g_h[i] = emb[x[i >> 7]*DD + (i & 127)]; return; }
    i -= NN*DD;
    if (i < 3*DD*H2D) { bsplit(gW1[i], g_w1hi[i], g_w1lo[i]); return; }
    i -= 3*DD*H2D;
    if (i < 3*H2D*DD) { bsplit(gW2[i], g_w2hi[i], g_w2lo[i]); return; }
    i -= 3*H2D*DD;
    if (i < DD*128) {
        int rw = i >> 7, cl = i & 127;
        float v = (cl < 50) ? pW1[rw*50 + cl] : 0.0f;
        bsplit(v, g_pwhi[i], g_pwlo[i]);
        return;
    }
    i -= DD*128;
    if (i < 128) g_pb1[i] = (i < 50) ? pb1[i] : 0.0f;
}

// ---------------- per-node gather (z = h + sum incoming) + bf16 split ----------------
__global__ void gather_kernel() {
    int w = threadIdx.x >> 5, lane = threadIdx.x & 31;
    int node = blockIdx.x*8 + w;
    const float4* h4 = (const float4*)g_h;
    float4 a = h4[(size_t)node*32 + lane];
    int e0 = g_off[node], e1 = g_off[node+1];
    for (int j = e0; j < e1; j++) {
        int s = g_srcl[j];
        float4 v = h4[(size_t)s*32 + lane];
        a.x += v.x; a.y += v.y; a.z += v.z; a.w += v.w;
    }
    __nv_bfloat162* ph = (__nv_bfloat162*)g_ahi;
    __nv_bfloat162* pl = (__nv_bfloat162*)g_alo;
    bf16 h0,l0,h1,l1;
    bsplit(a.x, h0, l0); bsplit(a.y, h1, l1);
    ph[(size_t)node*64 + lane*2]     = __halves2bfloat162(h0, h1);
    pl[(size_t)node*64 + lane*2]     = __halves2bfloat162(l0, l1);
    bsplit(a.z, h0, l0); bsplit(a.w, h1, l1);
    ph[(size_t)node*64 + lane*2 + 1] = __halves2bfloat162(h0, h1);
    pl[(size_t)node*64 + lane*2 + 1] = __halves2bfloat162(l0, l1);
}

// ---------------- resident-smem bf16-split GEMM, 128x128 block tile ----------------
// modes: 0 = GIN MLP layer1 (bias, relu, write bf16 split)
//        1 = GIN MLP layer2 mid (bias, BN, relu, write f32)
//        2 = GIN MLP layer2 last (bias, BN, write f32 + bf16 split + residue atomics)
//        3 = partitioner (bias, relu, fused W2 GEMV + softmax -> g_S)
#define SM_LDA 136
#define SM_LDO 132
#define SMEM_BYTES (4*128*SM_LDA*2)

template<int KCHUNKS>
__global__ void gemm128(const bf16* __restrict__ Ahi, const bf16* __restrict__ Alo,
                        const bf16* __restrict__ Bhi, const bf16* __restrict__ Blo,
                        const float* __restrict__ bias, const float* __restrict__ gamma,
                        const float* __restrict__ beta,
                        const float* __restrict__ pW2, const float* __restrict__ pb2,
                        float* __restrict__ outF, bf16* __restrict__ outHi,
                        bf16* __restrict__ outLo,
                        int Nn, int mode)
{
    constexpr int KTOT = KCHUNKS*128;
    extern __shared__ __align__(16) char smem[];
    bf16* sAh = (bf16*)smem;
    bf16* sAl = sAh + 128*SM_LDA;
    bf16* sBh = sAl + 128*SM_LDA;
    bf16* sBl = sBh + 128*SM_LDA;
    float* sO  = (float*)smem;                       // aliases sA after compute
    float* w2s = (float*)(smem + 128*SM_LDO*4);      // 255 floats, beyond sO

    int t = threadIdx.x, w = t >> 5;
    int wm = w & 3, wn = w >> 2;                     // 4x2 warp grid, warp tile 32x64
    int m0 = blockIdx.x*128, n0 = blockIdx.y*128;

    wmma::fragment<wmma::accumulator,16,16,16,float> acc[2][4];
    #pragma unroll
    for (int i = 0; i < 2; i++)
        #pragma unroll
        for (int j = 0; j < 4; j++)
            wmma::fill_fragment(acc[i][j], 0.0f);

    #pragma unroll
    for (int c = 0; c < KCHUNKS; c++) {
        // stage chunk: A[128 x 128] hi/lo, B[128 x 128] hi/lo
        // 128 rows x 16 uint4-chunks per array = 2048 vectors; 256 threads -> 8 iters
        #pragma unroll
        for (int i = 0; i < 8; i++) {
            int idx = t + i*256;
            int r = idx >> 4, p = idx & 15;
            *(uint4*)(sAh + r*SM_LDA + p*8) = *(const uint4*)(Ahi + (size_t)(m0 + r)*KTOT + c*128 + p*8);
            *(uint4*)(sAl + r*SM_LDA + p*8) = *(const uint4*)(Alo + (size_t)(m0 + r)*KTOT + c*128 + p*8);
            *(uint4*)(sBh + r*SM_LDA + p*8) = *(const uint4*)(Bhi + (size_t)(c*128 + r)*Nn + n0 + p*8);
            *(uint4*)(sBl + r*SM_LDA + p*8) = *(const uint4*)(Blo + (size_t)(c*128 + r)*Nn + n0 + p*8);
        }
        __syncthreads();

        #pragma unroll
        for (int s = 0; s < 3; s++) {
            const bf16* Ap = (s == 2) ? sAl : sAh;
            const bf16* Bp = (s == 1) ? sBl : sBh;
            #pragma unroll
            for (int kb = 0; kb < 8; kb++) {
                wmma::fragment<wmma::matrix_a,16,16,16,bf16,wmma::row_major> af[2];
                wmma::fragment<wmma::matrix_b,16,16,16,bf16,wmma::row_major> bfr[4];
                #pragma unroll
                for (int i = 0; i < 2; i++)
                    wmma::load_matrix_sync(af[i], Ap + (wm*32 + i*16)*SM_LDA + kb*16, SM_LDA);
                #pragma unroll
                for (int j = 0; j < 4; j++)
                    wmma::load_matrix_sync(bfr[j], Bp + (kb*16)*SM_LDA + wn*64 + j*16, SM_LDA);
                #pragma unroll
                for (int i = 0; i < 2; i++)
                    #pragma unroll
                    for (int j = 0; j < 4; j++)
                        wmma::mma_sync(acc[i][j], af[i], bfr[j], acc[i][j]);
            }
        }
        __syncthreads();
    }

    // spill accumulators to smem (aliases sA/sB, now dead)
    #pragma unroll
    for (int i = 0; i < 2; i++)
        #pragma unroll
        for (int j = 0; j < 4; j++)
            wmma::store_matrix_sync(sO + (wm*32 + i*16)*SM_LDO + wn*64 + j*16, acc[i][j],
                                    SM_LDO, wmma::mem_row_major);
    if (mode == 3 && t < 255) {
        w2s[t] = (t < 250) ? pW2[t] : pb2[t - 250];
    }
    __syncthreads();

    const float BNS = 0.99999500003749971f;  // 1/sqrt(1+1e-5)

    if (mode == 3) {
        if (t < 128) {
            float cr[50];
            #pragma unroll
            for (int j = 0; j < 50; j++)
                cr[j] = fmaxf(sO[t*SM_LDO + j] + bias[j], 0.0f);
            float l[5];
            #pragma unroll
            for (int k = 0; k < 5; k++) {
                float a = w2s[250 + k];
                #pragma unroll
                for (int j = 0; j < 50; j++) a += cr[j]*w2s[j*5 + k];
                l[k] = a;
            }
            float m = l[0];
            #pragma unroll
            for (int k = 1; k < 5; k++) m = fmaxf(m, l[k]);
            float e[5], s = 0.0f;
            #pragma unroll
            for (int k = 0; k < 5; k++) { e[k] = expf(l[k] - m); s += e[k]; }
            float inv = 1.0f/s;
            #pragma unroll
            for (int k = 0; k < 5; k++) g_S[(size_t)(m0 + t)*5 + k] = e[k]*inv;
        }
        return;
    }

    float rsum = 0.0f;
    int cidx = t & 127;
    #pragma unroll 4
    for (int i = 0; i < 64; i++) {
        int idx = t + i*256;
        int r = idx >> 7;                 // rows (t>>7) + 2i
        float v = sO[r*SM_LDO + cidx] + bias[n0 + cidx];
        if (mode != 0) v = v*(BNS*gamma[n0 + cidx]) + beta[n0 + cidx];
        if (mode != 2) v = fmaxf(v, 0.0f);
        size_t gi = (size_t)(m0 + r)*Nn + n0 + cidx;
        if (mode != 0) outF[gi] = v;
        if (mode != 1) {
            bf16 hi = __float2bfloat16(v);
            outHi[gi] = hi;
            outLo[gi] = __float2bfloat16(v - __bfloat162float(hi));
        }
        if (mode == 2) rsum += v;
    }
    if (mode == 2)
        atomicAdd(&g_res[(m0 >> 9)*128 + cidx], rsum);
}

// ---------------- soft-cluster pooling: cf[b,k,:] = S^T dense / (sumS+eps) ----------------
__global__ void cf_kernel() {
    int g = blockIdx.x, t = threadIdx.x;     // 640 threads
    __shared__ float sh[64*128];
    __shared__ float sS[64*5];
    int k = t >> 7, c = t & 127;
    float acc = 0.0f, ss = 0.0f;
    for (int ch = 0; ch < 8; ch++) {
        int nb = ch*64;
        const float* hb = g_h + ((size_t)g*NPGC + nb)*DD;
        for (int i = t; i < 64*128; i += 640) sh[i] = hb[i];
        const float* sb = g_S + ((size_t)g*NPGC + nb)*5;
        for (int i = t; i < 320; i += 640) sS[i] = sb[i];
        __syncthreads();
        for (int n2 = 0; n2 < 64; n2++) {
            float s = sS[n2*5 + k];
            acc += s*sh[n2*128 + c];
            ss  += s;
        }
        __syncthreads();
    }
    g_cf[((size_t)g*5 + k)*128 + c] = acc/(ss + 1e-6f);
}

// ---------------- VQ nearest codebook ----------------
__global__ void vq_kernel(const float* __restrict__ codebook) {
    int row = blockIdx.x;                    // 0..319
    int t = threadIdx.x, w = t >> 5, lane = t & 31;
    __shared__ __align__(16) float f[128];
    __shared__ float wbest[4];
    __shared__ int   widx[4];
    __shared__ int   bestidx;
    f[t] = g_cf[(size_t)row*128 + t];
    __syncthreads();
    float4 fv = ((const float4*)f)[lane];
    float best = 3.4e38f;
    int bi = 0;
    for (int rr = w; rr < CBN; rr += 4) {
        const float4* cb4 = (const float4*)(codebook + (size_t)rr*128);
        float4 cv = cb4[lane];
        float dx = cv.x - fv.x, dy = cv.y - fv.y, dz = cv.z - fv.z, dw = cv.w - fv.w;
        float d = dx*dx + dy*dy + dz*dz + dw*dw;
        #pragma unroll
        for (int o = 16; o; o >>= 1) d += __shfl_xor_sync(0xffffffff, d, o);
        if (d < best) { best = d; bi = rr; }
    }
    if (lane == 0) { wbest[w] = best; widx[w] = bi; }
    __syncthreads();
    if (t == 0) {
        float bb = wbest[0]; int ii = widx[0];
        for (int j = 1; j < 4; j++)
            if (wbest[j] < bb || (wbest[j] == bb && widx[j] < ii)) { bb = wbest[j]; ii = widx[j]; }
        bestidx = ii;
    }
    __syncthreads();
    g_zq[(size_t)row*128 + t] = codebook[(size_t)bestidx*128 + t];
}

// ---------------- fused attention + gate + classifier (per-graph) ----------------
__global__ void tail_kernel(const float* __restrict__ Wq, const float* __restrict__ Wk,
                            const float* __restrict__ Wv, const float* __restrict__ Wo,
                            const float* __restrict__ gW1, const float* __restrict__ gb1,
                            const float* __restrict__ gW2, const float* __restrict__ gb2,
                            const float* __restrict__ cW1, const float* __restrict__ cb1,
                            const float* __restrict__ cW2, const float* __restrict__ cb2,
                            const float* __restrict__ cW3, const float* __restrict__ cb3,
                            float* __restrict__ out)
{
    int g = blockIdx.x, t = threadIdx.x;     // 128 threads
    __shared__ float r[128], zq5[5*128], qv[128], kk[5*128], vv[5*128];
    __shared__ float sc[20], aw[20], attv[128], attn[128], g1[64], fused[128];
    __shared__ float z1[512], z2[256];

    r[t] = g_res[g*128 + t]*(1.0f/NPGC);
    #pragma unroll
    for (int j = 0; j < 5; j++) zq5[j*128 + t] = g_zq[((size_t)g*5 + j)*128 + t];
    __syncthreads();

    { // q
        float a = 0.0f;
        for (int k2 = 0; k2 < 128; k2++) a += r[k2]*Wq[k2*128 + t];
        qv[t] = a;
    }
    { // k
        float a5[5] = {0,0,0,0,0};
        for (int k2 = 0; k2 < 128; k2++) {
            float wv2 = Wk[k2*128 + t];
            #pragma unroll
            for (int j = 0; j < 5; j++) a5[j] += zq5[j*128 + k2]*wv2;
        }
        #pragma unroll
        for (int j = 0; j < 5; j++) kk[j*128 + t] = a5[j];
    }
    { // v
        float a5[5] = {0,0,0,0,0};
        for (int k2 = 0; k2 < 128; k2++) {
            float wv2 = Wv[k2*128 + t];
            #pragma unroll
            for (int j = 0; j < 5; j++) a5[j] += zq5[j*128 + k2]*wv2;
        }
        #pragma unroll
        for (int j = 0; j < 5; j++) vv[j*128 + t] = a5[j];
    }
    __syncthreads();

    if (t < 20) {
        int hh = t/5, j = t%5;
        float s = 0.0f;
        for (int d2 = 0; d2 < 32; d2++) s += qv[hh*32 + d2]*kk[j*128 + hh*32 + d2];
        sc[t] = s*0.17677669529663687f;      // 1/sqrt(32)
    }
    __syncthreads();
    if (t < 4) {
        float m = -1e30f;
        #pragma unroll
        for (int j = 0; j < 5; j++) m = fmaxf(m, sc[t*5 + j]);
        float e[5], s = 0.0f;
        #pragma unroll
        for (int j = 0; j < 5; j++) { e[j] = expf(sc[t*5 + j] - m); s += e[j]; }
        float inv = 1.0f/s;
        #pragma unroll
        for (int j = 0; j < 5; j++) aw[t*5 + j] = e[j]*inv;
    }
    __syncthreads();
    {
        int hh = t >> 5;
        float a = 0.0f;
        #pragma unroll
        for (int j = 0; j < 5; j++) a += aw[hh*5 + j]*vv[j*128 + t];
        attv[t] = a;
    }
    __syncthreads();
    {
        float a = 0.0f;
        for (int k2 = 0; k2 < 128; k2++) a += attv[k2]*Wo[k2*128 + t];
        attn[t] = a;
    }
    __syncthreads();
    if (t < 64) {
        float a = gb1[t];
        for (int k2 = 0; k2 < 128; k2++) a += r[k2]*gW1[k2*64 + t];
        for (int k2 = 0; k2 < 128; k2++) a += attn[k2]*gW1[(128 + k2)*64 + t];
        g1[t] = fmaxf(a, 0.0f);
    }
    __syncthreads();
    {
        float a = gb2[t];
        for (int k2 = 0; k2 < 64; k2++) a += g1[k2]*gW2[k2*128 + t];
        float gg = 1.0f/(1.0f + expf(-a));
        fused[t] = gg*r[t] + (1.0f - gg)*attn[t];
    }
    __syncthreads();
    for (int o = t; o < 512; o += 128) {
        float a = cb1[o];
        for (int k2 = 0; k2 < 128; k2++) a += fused[k2]*cW1[k2*512 + o];
        z1[o] = fmaxf(a, 0.0f);
    }
    __syncthreads();
    for (int o = t; o < 256; o += 128) {
        float a = cb2[o];
        for (int k2 = 0; k2 < 512; k2++) a += z1[k2]*cW2[k2*256 + o];
        z2[o] = fmaxf(a, 0.0f);
    }
    __syncthreads();
    if (t < 2) {
        float a = cb3[t];
        for (int k2 = 0; k2 < 256; k2++) a += z2[k2]*cW3[k2*2 + t];
        out[g*2 + t] = a;
    }
}

// ---------------- host launch ----------------
extern "C" void kernel_launch(void* const* d_in, const int* in_sizes, int n_in,
                              void* d_out, int out_size) {
    (void)in_sizes; (void)n_in; (void)out_size;
    const int*   x     = (const int*)d_in[0];
    const int*   ei    = (const int*)d_in[1];
    const float* emb   = (const float*)d_in[3];
    const float* gW1   = (const float*)d_in[4];
    const float* gb1v  = (const float*)d_in[5];
    const float* gW2   = (const float*)d_in[6];
    const float* gb2v  = (const float*)d_in[7];
    const float* bng   = (const float*)d_in[8];
    const float* bnb   = (const float*)d_in[9];
    const float* pW1   = (const float*)d_in[10];
    const float* pb1   = (const float*)d_in[11];
    const float* pW2   = (const float*)d_in[12];
    const float* pb2   = (const float*)d_in[13];
    const float* Wq    = (const float*)d_in[14];
    const float* Wk    = (const float*)d_in[15];
    const float* Wv    = (const float*)d_in[16];
    const float* Wo    = (const float*)d_in[17];
    const float* gateW1= (const float*)d_in[18];
    const float* gateb1= (const float*)d_in[19];
    const float* gateW2= (const float*)d_in[20];
    const float* gateb2= (const float*)d_in[21];
    const float* cbk   = (const float*)d_in[22];
    const float* cW1   = (const float*)d_in[23];
    const float* cb1   = (const float*)d_in[24];
    const float* cW2   = (const float*)d_in[25];
    const float* cb2   = (const float*)d_in[26];
    const float* cW3   = (const float*)d_in[27];
    const float* cb3   = (const float*)d_in[28];
    float* out = (float*)d_out;

    bf16 *ahi, *alo, *bhi, *blo, *w1hi, *w1lo, *w2hi, *w2lo, *pwhi, *pwlo;
    float *ph, *ppb1;
    cudaGetSymbolAddress((void**)&ahi,  g_ahi);
    cudaGetSymbolAddress((void**)&alo,  g_alo);
    cudaGetSymbolAddress((void**)&bhi,  g_bhi);
    cudaGetSymbolAddress((void**)&blo,  g_blo);
    cudaGetSymbolAddress((void**)&w1hi, g_w1hi);
    cudaGetSymbolAddress((void**)&w1lo, g_w1lo);
    cudaGetSymbolAddress((void**)&w2hi, g_w2hi);
    cudaGetSymbolAddress((void**)&w2lo, g_w2lo);
    cudaGetSymbolAddress((void**)&pwhi, g_pwhi);
    cudaGetSymbolAddress((void**)&pwlo, g_pwlo);
    cudaGetSymbolAddress((void**)&ph,   g_h);
    cudaGetSymbolAddress((void**)&ppb1, g_pb1);

    cudaFuncSetAttribute(gemm128<1>, cudaFuncAttributeMaxDynamicSharedMemorySize, SMEM_BYTES);
    cudaFuncSetAttribute(gemm128<2>, cudaFuncAttributeMaxDynamicSharedMemorySize, SMEM_BYTES);

    // CSR build
    zero_kernel   <<<(NN + BB*DD + 255)/256, 256>>>();
    count_kernel  <<<EE/256, 256>>>(ei);
    scan_kernel   <<<1, 1024>>>();
    scatter_kernel<<<EE/256, 256>>>(ei);

    // weight splits + embedding (merged)
    {
        int tot = NN*DD + 3*DD*H2D + 3*H2D*DD + DD*128 + 128;
        prep_embed<<<(tot + 255)/256, 256>>>(x, emb, gW1, gW2, pW1, pb1);
    }

    // 3 GIN layers
    for (int l = 0; l < 3; l++) {
        gather_kernel<<<NN/8, 256>>>();
        gemm128<1><<<dim3(NN/128, 2), 256, SMEM_BYTES>>>(
            ahi, alo, w1hi + (size_t)l*DD*H2D, w1lo + (size_t)l*DD*H2D,
            gb1v + l*H2D, nullptr, nullptr, nullptr, nullptr,
            nullptr, bhi, blo, H2D, /*mode*/0);
        gemm128<2><<<dim3(NN/128, 1), 256, SMEM_BYTES>>>(
            bhi, blo, w2hi + (size_t)l*H2D*DD, w2lo + (size_t)l*H2D*DD,
            gb2v + l*DD, bng + l*DD, bnb + l*DD, nullptr, nullptr,
            ph, ahi, alo, DD, /*mode*/ (l < 2) ? 1 : 2);
    }

    // partitioner GEMM + fused stage-2 (logits + softmax)
    gemm128<1><<<dim3(NN/128, 1), 256, SMEM_BYTES>>>(
        ahi, alo, pwhi, pwlo, ppb1, nullptr, nullptr, pW2, pb2,
        nullptr, nullptr, nullptr, 128, /*mode*/3);

    cf_kernel  <<<BB, 640>>>();
    vq_kernel  <<<BB*KCL, 128>>>(cbk);
    tail_kernel<<<BB, 128>>>(Wq, Wk, Wv, Wo, gateW1, gateb1, gateW2, gateb2,
                             cW1, cb1, cW2, cb2, cW3, cb3, out);
}